// round 14
// baseline (speedup 1.0000x reference)
#include <cuda_runtime.h>
#include <cuda_fp16.h>
#include <cstdint>
#include <math.h>

#define N_ITEMS 8192
#define DIM     64
#define BATCHSZ 4096
#define LN2F    0.69314718055994531f
#define INV_T   14.285714285714286f
#define ITLG2E  20.609947181438156f   /* (1/0.07) * log2(e) */
#define NTILES  2080                  /* 64*65/2 upper-triangle 128x128 tiles */
#define GRID_SY 304                   /* 2 CTAs/SM x 152 SMs */

// ---------------- device scratch (no allocations allowed) ----------------
// All scratch is self-cleaning: g_Z zeroed by lossrow after read, g_S/g_N by
// finalize. Static zero-init covers the first execution.
__device__ uint32_t g_fh[N_ITEMS * 32];   // normalized rows, half2-packed [row][32]
__device__ float    g_Z[N_ITEMS];         // exp-sums (atomic accumulated)
__device__ float    g_S[56 * 64];         // per-class feature sums
__device__ int      g_N[56];              // per-class counts
__device__ float    g_partial[512];       // per-CTA loss partials

// ---------------- helpers --------------------------------------------------
static __device__ __forceinline__ uint32_t smem_u32(const void* p) {
    uint32_t a;
    asm("{ .reg .u64 t; cvta.to.shared.u64 t, %1; cvt.u32.u64 %0, t; }" : "=r"(a) : "l"(p));
    return a;
}
static __device__ __forceinline__ float ex2f(float x) {
    float y; asm("ex2.approx.ftz.f32 %0, %1;" : "=f"(y) : "f"(x)); return y;
}
static __device__ __forceinline__ float lg2f(float x) {
    float y; asm("lg2.approx.ftz.f32 %0, %1;" : "=f"(y) : "f"(x)); return y;
}
static __device__ __forceinline__ void cp16(uint32_t dst, const void* src) {
    asm volatile("cp.async.cg.shared.global [%0], [%1], 16;" :: "r"(dst), "l"(src));
}
#define CP_COMMIT() asm volatile("cp.async.commit_group;" ::: "memory")
static __device__ __forceinline__ void ldsm4(uint32_t* r, uint32_t addr) {
    asm volatile("ldmatrix.sync.aligned.m8n8.x4.shared.b16 {%0,%1,%2,%3}, [%4];"
                 : "=r"(r[0]), "=r"(r[1]), "=r"(r[2]), "=r"(r[3]) : "r"(addr));
}
static __device__ __forceinline__ void mma16816(float* d, const uint32_t* a,
                                                uint32_t b0, uint32_t b1) {
    asm volatile("mma.sync.aligned.m16n8k16.row.col.f32.f16.f16.f32 "
                 "{%0,%1,%2,%3}, {%4,%5,%6,%7}, {%8,%9}, {%0,%1,%2,%3};"
                 : "+f"(d[0]), "+f"(d[1]), "+f"(d[2]), "+f"(d[3])
                 : "r"(a[0]), "r"(a[1]), "r"(a[2]), "r"(a[3]), "r"(b0), "r"(b1));
}

// ---------------- kernel 1: fused normalize + rating + class sums ----------
// 448 CTAs x 512 thr:
//   blocks [0,256):   normalize 32 rows each (half-warp per row)
//   blocks [256,384): rating, 32 per block
//   blocks [384,448): class sums (self-normalizing from emb, fp16-rounded)
__global__ __launch_bounds__(512) void prep_kernel(const float* __restrict__ emb,
                                                   const int* __restrict__ idx,
                                                   const float* __restrict__ w,
                                                   const float* __restrict__ bias,
                                                   float* __restrict__ out,
                                                   const int* __restrict__ labels) {
    __shared__ uint32_t sf[128 * 32];   // 16 KB: fp16x2 normalized rows (classsum)
    __shared__ int      sl[128];
    int bid = blockIdx.x;
    int tid = threadIdx.x;
    if (bid < 256) {
        int hw = tid >> 4, hl = tid & 15;
        int row = bid * 32 + hw;
        float4 v = reinterpret_cast<const float4*>(emb + (size_t)row * DIM)[hl];
        float ss = v.x * v.x + v.y * v.y + v.z * v.z + v.w * v.w;
        #pragma unroll
        for (int o = 8; o; o >>= 1) ss += __shfl_xor_sync(0xFFFFFFFFu, ss, o);
        float inv = 1.0f / fmaxf(sqrtf(ss), 1e-12f);
        __half2 h0 = __floats2half2_rn(v.x * inv, v.y * inv);
        __half2 h1 = __floats2half2_rn(v.z * inv, v.w * inv);
        uint2 u;
        u.x = *reinterpret_cast<uint32_t*>(&h0);
        u.y = *reinterpret_cast<uint32_t*>(&h1);
        reinterpret_cast<uint2*>(g_fh + (size_t)row * 32)[hl] = u;
    } else if (bid < 384) {
        int hw = tid >> 4, hl = tid & 15;
        int r = (bid - 256) * 32 + hw;
        int it = idx[r];
        float4 v  = reinterpret_cast<const float4*>(emb + (size_t)it * DIM)[hl];
        float4 ww = reinterpret_cast<const float4*>(w)[hl];
        float s = v.x * ww.x + v.y * ww.y + v.z * ww.z + v.w * ww.w;
        #pragma unroll
        for (int o = 8; o; o >>= 1) s += __shfl_xor_sync(0xFFFFFFFFu, s, o);
        if (hl == 0) out[r] = 1.0f / (1.0f + __expf(-(s + bias[0])));
    } else {
        int b = bid - 384;
        int wd = tid >> 5, lane = tid & 31;
        // self-normalize 128 rows (fp16-rounded, same quantization as g_fh path)
        int hw = tid >> 4, hl = tid & 15;
        #pragma unroll
        for (int k = 0; k < 4; k++) {
            int rl = k * 32 + hw;
            int row = b * 128 + rl;
            float4 v = reinterpret_cast<const float4*>(emb + (size_t)row * DIM)[hl];
            float ss = v.x * v.x + v.y * v.y + v.z * v.z + v.w * v.w;
            #pragma unroll
            for (int o = 8; o; o >>= 1) ss += __shfl_xor_sync(0xFFFFFFFFu, ss, o);
            float inv = 1.0f / fmaxf(sqrtf(ss), 1e-12f);
            __half2 h0 = __floats2half2_rn(v.x * inv, v.y * inv);
            __half2 h1 = __floats2half2_rn(v.z * inv, v.w * inv);
            sf[rl * 32 + 2 * hl]     = *reinterpret_cast<uint32_t*>(&h0);
            sf[rl * 32 + 2 * hl + 1] = *reinterpret_cast<uint32_t*>(&h1);
        }
        (void)wd; (void)lane;
        if (tid < 128) sl[tid] = labels[b * 128 + tid];
        __syncthreads();
        int d = tid & 63, g = tid >> 6, c0 = g * 7;
        float a[7] = {0, 0, 0, 0, 0, 0, 0};
        int   n[7] = {0, 0, 0, 0, 0, 0, 0};
        for (int r = 0; r < 128; r++) {
            int rel = sl[r] - c0;
            if ((unsigned)rel < 7u) {
                uint32_t p = sf[r * 32 + (d >> 1)];
                __half2 h = *reinterpret_cast<__half2*>(&p);
                float v = (d & 1) ? __high2float(h) : __low2float(h);
                #pragma unroll
                for (int q = 0; q < 7; q++) if (rel == q) { a[q] += v; n[q]++; }
            }
        }
        #pragma unroll
        for (int q = 0; q < 7; q++) {
            atomicAdd(&g_S[(c0 + q) * 64 + d], a[q]);
            if (d == 0) atomicAdd(&g_N[c0 + q], n[q]);
        }
    }
}

// ---------------- kernel 2: symmetric Z-only GEMM, chunked + A reuse -------
static __device__ __forceinline__ void decode_tile(int w, int& ti, int& tj) {
    float disc = 16641.0f - 8.0f * (float)w;
    int t = (int)((129.0f - sqrtf(disc)) * 0.5f);
    if (t > 63) t = 63;
    if (t < 0) t = 0;
    while (t > 0 && (t * (129 - t)) / 2 > w) t--;
    while (t < 63 && ((t + 1) * (128 - t)) / 2 <= w) t++;
    ti = t;
    tj = t + (w - (t * (129 - t)) / 2);
}
static __device__ __forceinline__ void load_band(uint32_t sdst, int band, int tid) {
    const char* gsrc = (const char*)g_fh + (size_t)band * 16384;
    #pragma unroll
    for (int i = tid; i < 1024; i += 512) {
        uint32_t off = ((i >> 3) * 128) + ((i & 7) * 16);
        uint32_t sw  = off ^ ((off >> 3) & 0x70);
        cp16(sdst + sw, gsrc + off);
    }
}

__global__ __launch_bounds__(512, 2) void supcon_kernel() {
    extern __shared__ char dyn[];
    float* stage_col = reinterpret_cast<float*>(dyn + 65536);   // [16][64]
    float* stage_row = stage_col + 16 * 64;                     // [2][128]

    const int tid  = threadIdx.x;
    const int w    = tid >> 5;
    const int lane = tid & 31;
    const int wr   = w & 7;
    const int wc   = w >> 3;
    const uint32_t sbase = smem_u32(dyn);
    const int bnoff = (((lane >> 4) & 1) << 3) + (lane & 7);
    const uint32_t bksel = (uint32_t)((lane >> 3) & 1);
    const float negM = -ITLG2E;

    const int start = (int)(((long long)blockIdx.x * NTILES) / GRID_SY);
    const int end   = (int)(((long long)(blockIdx.x + 1) * NTILES) / GRID_SY);

    int ti, tj;
    decode_tile(start, ti, tj);
    int aslot = 0, bslot = 0;
    bool bIsA = (ti == tj);
    load_band(sbase, ti, tid);
    if (!bIsA) load_band(sbase + 32768, tj, tid);
    CP_COMMIT();

    bool aNew = true;
    uint32_t ah[4][4];

    for (int job = start; job < end; job++) {
        bool loadA = false, loadB = false, nbIsA = bIsA;
        int tin = ti, tjn = tj;
        if (job + 1 < end) {
            decode_tile(job + 1, tin, tjn);
            nbIsA = (tin == tjn);
            loadA = (tin != ti);
            loadB = !nbIsA;
            if (loadA) load_band(sbase + (uint32_t)(aslot ^ 1) * 16384, tin, tid);
            if (loadB) load_band(sbase + 32768 + (uint32_t)(bslot ^ 1) * 16384, tjn, tid);
        }
        CP_COMMIT();
        asm volatile("cp.async.wait_group 1;" ::: "memory");
        __syncthreads();                      // current tile resident

        const uint32_t Ab = sbase + (uint32_t)aslot * 16384;
        const uint32_t Bb = bIsA ? Ab : (sbase + 32768 + (uint32_t)bslot * 16384);

        if (aNew) {
            int arow = wr * 16 + (lane & 15);
            uint32_t rbase = Ab + (uint32_t)arow * 128;
            #pragma unroll
            for (int ks = 0; ks < 4; ks++) {
                uint32_t c = (uint32_t)(ks * 2 + (lane >> 4));
                ldsm4(ah[ks], rbase + ((c ^ (arow & 7)) << 4));
            }
        }

        float rowZ0 = 0.f, rowZ1 = 0.f;
        #pragma unroll
        for (int ntp = 0; ntp < 4; ntp++) {
            float a0[4] = {0.f, 0.f, 0.f, 0.f};
            float a1[4] = {0.f, 0.f, 0.f, 0.f};
            int n = wc * 64 + ntp * 16 + bnoff;
            uint32_t nb = Bb + (uint32_t)n * 128;
            #pragma unroll
            for (int ks = 0; ks < 4; ks++) {
                uint32_t c = (uint32_t)(ks * 2) + bksel;
                uint32_t bb[4];
                ldsm4(bb, nb + ((c ^ (n & 7)) << 4));
                mma16816(a0, ah[ks], bb[0], bb[1]);
                mma16816(a1, ah[ks], bb[2], bb[3]);
            }
            float e00 = ex2f(fmaf(a0[0], ITLG2E, negM));
            float e01 = ex2f(fmaf(a0[1], ITLG2E, negM));
            float e10 = ex2f(fmaf(a0[2], ITLG2E, negM));
            float e11 = ex2f(fmaf(a0[3], ITLG2E, negM));
            float f00 = ex2f(fmaf(a1[0], ITLG2E, negM));
            float f01 = ex2f(fmaf(a1[1], ITLG2E, negM));
            float f10 = ex2f(fmaf(a1[2], ITLG2E, negM));
            float f11 = ex2f(fmaf(a1[3], ITLG2E, negM));
            rowZ0 += (e00 + e01) + (f00 + f01);
            rowZ1 += (e10 + e11) + (f10 + f11);
            float cz0 = e00 + e10, cz1 = e01 + e11;
            float cz2 = f00 + f10, cz3 = f01 + f11;
            #pragma unroll
            for (int off = 4; off <= 16; off <<= 1) {
                cz0 += __shfl_xor_sync(0xFFFFFFFFu, cz0, off);
                cz1 += __shfl_xor_sync(0xFFFFFFFFu, cz1, off);
                cz2 += __shfl_xor_sync(0xFFFFFFFFu, cz2, off);
                cz3 += __shfl_xor_sync(0xFFFFFFFFu, cz3, off);
            }
            if (lane < 4) {
                int cl = ntp * 16 + 2 * lane;
                stage_col[w * 64 + cl]     = cz0;
                stage_col[w * 64 + cl + 1] = cz1;
                stage_col[w * 64 + cl + 8] = cz2;
                stage_col[w * 64 + cl + 9] = cz3;
            }
        }
        #pragma unroll
        for (int off = 1; off <= 2; off <<= 1) {
            rowZ0 += __shfl_xor_sync(0xFFFFFFFFu, rowZ0, off);
            rowZ1 += __shfl_xor_sync(0xFFFFFFFFu, rowZ1, off);
        }
        if ((lane & 3) == 0) {
            int r0 = wr * 16 + (lane >> 2);
            stage_row[wc * 128 + r0]     = rowZ0;
            stage_row[wc * 128 + r0 + 8] = rowZ1;
        }
        __syncthreads();                      // stages complete
        if (tid < 128) {
            if (ti != tj) {
                int whalf = (tid >> 6) * 8;
                int cl = tid & 63;
                float v = 0.f;
                #pragma unroll
                for (int k = 0; k < 8; k++) v += stage_col[(whalf + k) * 64 + cl];
                atomicAdd(&g_Z[tj * 128 + tid], v);
            }
        } else if (tid < 256) {
            int r = tid - 128;
            atomicAdd(&g_Z[ti * 128 + r], stage_row[r] + stage_row[128 + r]);
        }
        if (loadA) aslot ^= 1;
        if (loadB) bslot ^= 1;
        aNew = loadA;
        ti = tin; tj = tjn; bIsA = nbIsA;
    }
}

// ---------------- kernel 3: per-row loss, warp-per-row ----------------------
// Also zeroes g_Z after reading (self-cleaning for graph replay).
__global__ __launch_bounds__(512) void lossrow_kernel(const int* __restrict__ labels) {
    __shared__ float red[16];
    int tid  = threadIdx.x;
    int w    = tid >> 5;
    int lane = tid & 31;
    int r    = blockIdx.x * 16 + w;

    int lab = labels[r];
    uint32_t p = g_fh[(size_t)r * 32 + lane];          // coalesced 128B per row
    __half2 h = *reinterpret_cast<__half2*>(&p);
    float f0 = __low2float(h), f1 = __high2float(h);
    float S0 = g_S[lab * 64 + 2 * lane];
    float S1 = g_S[lab * 64 + 2 * lane + 1];
    float sii = f0 * f0 + f1 * f1;
    float di  = f0 * S0 + f1 * S1;
    #pragma unroll
    for (int o = 16; o; o >>= 1) {
        sii += __shfl_xor_sync(0xFFFFFFFFu, sii, o);
        di  += __shfl_xor_sync(0xFFFFFFFFu, di, o);
    }
    if (lane == 0) {
        float Zr  = g_Z[r];
        g_Z[r] = 0.f;                                  // self-clean for next replay
        float Cc  = (float)g_N[lab] - 1.0f;
        float eD  = ex2f((sii - 1.0f) * ITLG2E);       // diagonal exp term
        float Zv  = Zr - eD;                           // exclude self
        float Pln = (di - sii - Cc) * INV_T;           // positive-logit sum (ln)
        float lnZ = lg2f(Zv + 1e-6f) * LN2F;
        red[w] = (Pln - Cc * lnZ) / (Cc + 1e-6f);
    }
    __syncthreads();
    if (tid == 0) {
        float s = 0.f;
        #pragma unroll
        for (int i = 0; i < 16; i++) s += red[i];
        g_partial[blockIdx.x] = s;
    }
}

// ---------------- kernel 4: finalize + scratch re-zero ----------------------
__global__ __launch_bounds__(512) void finalize_kernel(float* __restrict__ out, int out_size) {
    __shared__ float s2[16];
    int tid = threadIdx.x;
    float v = g_partial[tid];
    #pragma unroll
    for (int o = 16; o; o >>= 1) v += __shfl_xor_sync(0xFFFFFFFFu, v, o);
    if ((tid & 31) == 0) s2[tid >> 5] = v;
    __syncthreads();
    if (tid == 0) {
        float s = 0.f;
        #pragma unroll
        for (int i = 0; i < 16; i++) s += s2[i];
        float loss = -(s / (float)N_ITEMS);
        for (int i = BATCHSZ; i < out_size; i++) out[i] = loss;
    }
    // self-clean class sums for the next replay
    for (int i = tid; i < 3584; i += 512) g_S[i] = 0.f;
    if (tid < 56) g_N[tid] = 0;
}

// ---------------- launch ----------------------------------------------------
extern "C" void kernel_launch(void* const* d_in, const int* in_sizes, int n_in,
                              void* d_out, int out_size) {
    const int*   idx    = (const int*)d_in[0];
    const int*   labels = (const int*)d_in[1];
    const float* emb    = (const float*)d_in[2];
    const float* w      = (const float*)d_in[3];
    const float* b      = (const float*)d_in[4];
    float* out = (float*)d_out;

    const int SMEM = 65536 + 16 * 64 * 4 + 2 * 128 * 4;   // 70656 B
    cudaFuncSetAttribute(supcon_kernel, cudaFuncAttributeMaxDynamicSharedMemorySize, SMEM);

    prep_kernel<<<448, 512>>>(emb, idx, w, b, out, labels);
    supcon_kernel<<<GRID_SY, 512, SMEM>>>();
    lossrow_kernel<<<512, 512>>>(labels);
    finalize_kernel<<<1, 512>>>(out, out_size);
}

// round 15
// speedup vs baseline: 1.1968x; 1.1968x over previous
#include <cuda_runtime.h>
#include <cuda_fp16.h>
#include <cstdint>
#include <math.h>

#define N_ITEMS 8192
#define DIM     64
#define BATCHSZ 4096
#define LN2F    0.69314718055994531f
#define INV_T   14.285714285714286f
#define ITLG2E  20.609947181438156f   /* (1/0.07) * log2(e) */
#define NTILES  2080                  /* 64*65/2 upper-triangle 128x128 tiles */
#define GRID_SY 304                   /* 2 CTAs/SM x 152 SMs */

// ---------------- device scratch (no allocations allowed) ----------------
__device__ uint32_t g_fh[N_ITEMS * 32];   // normalized rows, half2-packed [row][32]
__device__ float    g_Z[N_ITEMS];         // exp-sums (atomic accumulated)
__device__ float    g_S[56 * 64];         // per-class feature sums
__device__ int      g_N[56];              // per-class counts
__device__ float    g_partial[512];       // per-CTA loss partials
__device__ unsigned int g_ticket = 0;     // last-CTA ticket (reset each run)

// ---------------- helpers --------------------------------------------------
static __device__ __forceinline__ uint32_t smem_u32(const void* p) {
    uint32_t a;
    asm("{ .reg .u64 t; cvta.to.shared.u64 t, %1; cvt.u32.u64 %0, t; }" : "=r"(a) : "l"(p));
    return a;
}
static __device__ __forceinline__ float ex2f(float x) {
    float y; asm("ex2.approx.ftz.f32 %0, %1;" : "=f"(y) : "f"(x)); return y;
}
static __device__ __forceinline__ float lg2f(float x) {
    float y; asm("lg2.approx.ftz.f32 %0, %1;" : "=f"(y) : "f"(x)); return y;
}
static __device__ __forceinline__ float ldcg(const float* p) {
    float v; asm volatile("ld.global.cg.f32 %0, [%1];" : "=f"(v) : "l"(p)); return v;
}
static __device__ __forceinline__ void cp16(uint32_t dst, const void* src) {
    asm volatile("cp.async.cg.shared.global [%0], [%1], 16;" :: "r"(dst), "l"(src));
}
#define CP_COMMIT() asm volatile("cp.async.commit_group;" ::: "memory")
static __device__ __forceinline__ void ldsm4(uint32_t* r, uint32_t addr) {
    asm volatile("ldmatrix.sync.aligned.m8n8.x4.shared.b16 {%0,%1,%2,%3}, [%4];"
                 : "=r"(r[0]), "=r"(r[1]), "=r"(r[2]), "=r"(r[3]) : "r"(addr));
}
static __device__ __forceinline__ void mma16816(float* d, const uint32_t* a,
                                                uint32_t b0, uint32_t b1) {
    asm volatile("mma.sync.aligned.m16n8k16.row.col.f32.f16.f16.f32 "
                 "{%0,%1,%2,%3}, {%4,%5,%6,%7}, {%8,%9}, {%0,%1,%2,%3};"
                 : "+f"(d[0]), "+f"(d[1]), "+f"(d[2]), "+f"(d[3])
                 : "r"(a[0]), "r"(a[1]), "r"(a[2]), "r"(a[3]), "r"(b0), "r"(b1));
}

// ---------------- kernel 1: normalize + rating + zero scratch --------------
// half-warp (16 lanes) per row: blocks 0..511 normalize (16 rows/CTA),
// 512..767 rating, 768..779 zero scratch. 780 CTAs -> single wave.
__global__ __launch_bounds__(256) void prep_kernel(const float* __restrict__ emb,
                                                   const int* __restrict__ idx,
                                                   const float* __restrict__ w,
                                                   const float* __restrict__ bias,
                                                   float* __restrict__ out) {
    int bid = blockIdx.x;
    int hw  = threadIdx.x >> 4;      // half-warp in block (0..15)
    int hl  = threadIdx.x & 15;      // lane in half-warp
    if (bid < 512) {
        int row = bid * 16 + hw;
        float4 v = reinterpret_cast<const float4*>(emb + (size_t)row * DIM)[hl];
        float ss = v.x * v.x + v.y * v.y + v.z * v.z + v.w * v.w;
        #pragma unroll
        for (int o = 8; o; o >>= 1) ss += __shfl_xor_sync(0xFFFFFFFFu, ss, o);
        float inv = 1.0f / fmaxf(sqrtf(ss), 1e-12f);
        __half2 h0 = __floats2half2_rn(v.x * inv, v.y * inv);
        __half2 h1 = __floats2half2_rn(v.z * inv, v.w * inv);
        uint2 u;
        u.x = *reinterpret_cast<uint32_t*>(&h0);
        u.y = *reinterpret_cast<uint32_t*>(&h1);
        reinterpret_cast<uint2*>(g_fh + (size_t)row * 32)[hl] = u;
    } else if (bid < 768) {
        int r = (bid - 512) * 16 + hw;
        int it = idx[r];
        float4 v  = reinterpret_cast<const float4*>(emb + (size_t)it * DIM)[hl];
        float4 ww = reinterpret_cast<const float4*>(w)[hl];
        float s = v.x * ww.x + v.y * ww.y + v.z * ww.z + v.w * ww.w;
        #pragma unroll
        for (int o = 8; o; o >>= 1) s += __shfl_xor_sync(0xFFFFFFFFu, s, o);
        if (hl == 0) out[r] = 1.0f / (1.0f + __expf(-(s + bias[0])));
    } else {
        int flat = (bid - 768) * 1024 + threadIdx.x * 4;
        #pragma unroll
        for (int k = 0; k < 4; k++) {
            int f = flat + k;
            if (f < N_ITEMS) g_Z[f] = 0.f;
            else if (f < N_ITEMS + 3584) g_S[f - N_ITEMS] = 0.f;
            else if (f < N_ITEMS + 3584 + 56) g_N[f - N_ITEMS - 3584] = 0;
        }
    }
}

// ---------------- kernel 2: per-class feature sums (128 CTAs, 64 rows) -----
__global__ __launch_bounds__(512) void classsum_kernel(const int* __restrict__ labels) {
    __shared__ int sl[64];
    int tid = threadIdx.x;
    int d = tid & 63, g = tid >> 6, c0 = g * 7;
    if (tid < 64) sl[tid] = labels[blockIdx.x * 64 + tid];
    __syncthreads();
    float a[7] = {0, 0, 0, 0, 0, 0, 0};
    int   n[7] = {0, 0, 0, 0, 0, 0, 0};
    for (int r = 0; r < 64; r++) {
        int rel = sl[r] - c0;
        if ((unsigned)rel < 7u) {
            uint32_t p = g_fh[(size_t)(blockIdx.x * 64 + r) * 32 + (d >> 1)];
            __half2 h = *reinterpret_cast<__half2*>(&p);
            float v = (d & 1) ? __high2float(h) : __low2float(h);
            #pragma unroll
            for (int q = 0; q < 7; q++) if (rel == q) { a[q] += v; n[q]++; }
        }
    }
    #pragma unroll
    for (int q = 0; q < 7; q++) {
        atomicAdd(&g_S[(c0 + q) * 64 + d], a[q]);
        if (d == 0) atomicAdd(&g_N[c0 + q], n[q]);
    }
}

// ---------------- kernel 3: symmetric Z-only GEMM, chunked + A reuse -------
static __device__ __forceinline__ void decode_tile(int w, int& ti, int& tj) {
    float disc = 16641.0f - 8.0f * (float)w;
    int t = (int)((129.0f - sqrtf(disc)) * 0.5f);
    if (t > 63) t = 63;
    if (t < 0) t = 0;
    while (t > 0 && (t * (129 - t)) / 2 > w) t--;
    while (t < 63 && ((t + 1) * (128 - t)) / 2 <= w) t++;
    ti = t;
    tj = t + (w - (t * (129 - t)) / 2);
}
static __device__ __forceinline__ void load_band(uint32_t sdst, int band, int tid) {
    const char* gsrc = (const char*)g_fh + (size_t)band * 16384;
    #pragma unroll
    for (int i = tid; i < 1024; i += 512) {
        uint32_t off = ((i >> 3) * 128) + ((i & 7) * 16);
        uint32_t sw  = off ^ ((off >> 3) & 0x70);
        cp16(sdst + sw, gsrc + off);
    }
}

__global__ __launch_bounds__(512, 2) void supcon_kernel() {
    extern __shared__ char dyn[];
    float* stage_col = reinterpret_cast<float*>(dyn + 65536);   // [16][64]
    float* stage_row = stage_col + 16 * 64;                     // [2][128]

    const int tid  = threadIdx.x;
    const int w    = tid >> 5;
    const int lane = tid & 31;
    const int wr   = w & 7;
    const int wc   = w >> 3;
    const uint32_t sbase = smem_u32(dyn);
    const int bnoff = (((lane >> 4) & 1) << 3) + (lane & 7);
    const uint32_t bksel = (uint32_t)((lane >> 3) & 1);
    const float negM = -ITLG2E;

    const int start = (int)(((long long)blockIdx.x * NTILES) / GRID_SY);
    const int end   = (int)(((long long)(blockIdx.x + 1) * NTILES) / GRID_SY);

    int ti, tj;
    decode_tile(start, ti, tj);
    int aslot = 0, bslot = 0;
    bool bIsA = (ti == tj);
    load_band(sbase, ti, tid);
    if (!bIsA) load_band(sbase + 32768, tj, tid);
    CP_COMMIT();

    bool aNew = true;
    uint32_t ah[4][4];

    for (int job = start; job < end; job++) {
        bool loadA = false, loadB = false, nbIsA = bIsA;
        int tin = ti, tjn = tj;
        if (job + 1 < end) {
            decode_tile(job + 1, tin, tjn);
            nbIsA = (tin == tjn);
            loadA = (tin != ti);
            loadB = !nbIsA;
            if (loadA) load_band(sbase + (uint32_t)(aslot ^ 1) * 16384, tin, tid);
            if (loadB) load_band(sbase + 32768 + (uint32_t)(bslot ^ 1) * 16384, tjn, tid);
        }
        CP_COMMIT();
        asm volatile("cp.async.wait_group 1;" ::: "memory");
        __syncthreads();                      // current tile resident

        const uint32_t Ab = sbase + (uint32_t)aslot * 16384;
        const uint32_t Bb = bIsA ? Ab : (sbase + 32768 + (uint32_t)bslot * 16384);

        if (aNew) {
            int arow = wr * 16 + (lane & 15);
            uint32_t rbase = Ab + (uint32_t)arow * 128;
            #pragma unroll
            for (int ks = 0; ks < 4; ks++) {
                uint32_t c = (uint32_t)(ks * 2 + (lane >> 4));
                ldsm4(ah[ks], rbase + ((c ^ (arow & 7)) << 4));
            }
        }

        float rowZ0 = 0.f, rowZ1 = 0.f;
        #pragma unroll
        for (int ntp = 0; ntp < 4; ntp++) {
            float a0[4] = {0.f, 0.f, 0.f, 0.f};
            float a1[4] = {0.f, 0.f, 0.f, 0.f};
            int n = wc * 64 + ntp * 16 + bnoff;
            uint32_t nb = Bb + (uint32_t)n * 128;
            #pragma unroll
            for (int ks = 0; ks < 4; ks++) {
                uint32_t c = (uint32_t)(ks * 2) + bksel;
                uint32_t bb[4];
                ldsm4(bb, nb + ((c ^ (n & 7)) << 4));
                mma16816(a0, ah[ks], bb[0], bb[1]);
                mma16816(a1, ah[ks], bb[2], bb[3]);
            }
            float e00 = ex2f(fmaf(a0[0], ITLG2E, negM));
            float e01 = ex2f(fmaf(a0[1], ITLG2E, negM));
            float e10 = ex2f(fmaf(a0[2], ITLG2E, negM));
            float e11 = ex2f(fmaf(a0[3], ITLG2E, negM));
            float f00 = ex2f(fmaf(a1[0], ITLG2E, negM));
            float f01 = ex2f(fmaf(a1[1], ITLG2E, negM));
            float f10 = ex2f(fmaf(a1[2], ITLG2E, negM));
            float f11 = ex2f(fmaf(a1[3], ITLG2E, negM));
            rowZ0 += (e00 + e01) + (f00 + f01);
            rowZ1 += (e10 + e11) + (f10 + f11);
            float cz0 = e00 + e10, cz1 = e01 + e11;
            float cz2 = f00 + f10, cz3 = f01 + f11;
            #pragma unroll
            for (int off = 4; off <= 16; off <<= 1) {
                cz0 += __shfl_xor_sync(0xFFFFFFFFu, cz0, off);
                cz1 += __shfl_xor_sync(0xFFFFFFFFu, cz1, off);
                cz2 += __shfl_xor_sync(0xFFFFFFFFu, cz2, off);
                cz3 += __shfl_xor_sync(0xFFFFFFFFu, cz3, off);
            }
            if (lane < 4) {
                int cl = ntp * 16 + 2 * lane;
                stage_col[w * 64 + cl]     = cz0;
                stage_col[w * 64 + cl + 1] = cz1;
                stage_col[w * 64 + cl + 8] = cz2;
                stage_col[w * 64 + cl + 9] = cz3;
            }
        }
        #pragma unroll
        for (int off = 1; off <= 2; off <<= 1) {
            rowZ0 += __shfl_xor_sync(0xFFFFFFFFu, rowZ0, off);
            rowZ1 += __shfl_xor_sync(0xFFFFFFFFu, rowZ1, off);
        }
        if ((lane & 3) == 0) {
            int r0 = wr * 16 + (lane >> 2);
            stage_row[wc * 128 + r0]     = rowZ0;
            stage_row[wc * 128 + r0 + 8] = rowZ1;
        }
        __syncthreads();                      // stages complete
        if (tid < 128) {
            if (ti != tj) {
                int whalf = (tid >> 6) * 8;
                int cl = tid & 63;
                float v = 0.f;
                #pragma unroll
                for (int k = 0; k < 8; k++) v += stage_col[(whalf + k) * 64 + cl];
                atomicAdd(&g_Z[tj * 128 + tid], v);
            }
        } else if (tid < 256) {
            int r = tid - 128;
            atomicAdd(&g_Z[ti * 128 + r], stage_row[r] + stage_row[128 + r]);
        }
        if (loadA) aslot ^= 1;
        if (loadB) bslot ^= 1;
        aNew = loadA;
        ti = tin; tj = tjn; bIsA = nbIsA;
    }
}

// ---------------- kernel 4: per-row loss + fused last-CTA finalize ----------
// 512 CTAs x 512 thr (16 warps); warp handles exactly 1 row.
__global__ __launch_bounds__(512) void lossrow_kernel(const int* __restrict__ labels,
                                                      float* __restrict__ out,
                                                      int out_size) {
    __shared__ float red[16];
    __shared__ int   slast;
    __shared__ float s2[16];
    int tid  = threadIdx.x;
    int w    = tid >> 5;
    int lane = tid & 31;
    int r    = blockIdx.x * 16 + w;

    int lab = labels[r];
    uint32_t p = g_fh[(size_t)r * 32 + lane];          // coalesced 128B per row
    __half2 h = *reinterpret_cast<__half2*>(&p);
    float f0 = __low2float(h), f1 = __high2float(h);
    float S0 = g_S[lab * 64 + 2 * lane];
    float S1 = g_S[lab * 64 + 2 * lane + 1];
    float sii = f0 * f0 + f1 * f1;
    float di  = f0 * S0 + f1 * S1;
    #pragma unroll
    for (int o = 16; o; o >>= 1) {
        sii += __shfl_xor_sync(0xFFFFFFFFu, sii, o);
        di  += __shfl_xor_sync(0xFFFFFFFFu, di, o);
    }
    if (lane == 0) {
        float Cc  = (float)g_N[lab] - 1.0f;
        float eD  = ex2f((sii - 1.0f) * ITLG2E);       // diagonal exp term
        float Zv  = g_Z[r] - eD;                       // exclude self
        float Pln = (di - sii - Cc) * INV_T;           // positive-logit sum (ln)
        float lnZ = lg2f(Zv + 1e-6f) * LN2F;
        red[w] = (Pln - Cc * lnZ) / (Cc + 1e-6f);
    }
    __syncthreads();
    if (tid == 0) {
        float s = 0.f;
        #pragma unroll
        for (int i = 0; i < 16; i++) s += red[i];
        g_partial[blockIdx.x] = s;
        __threadfence();
        unsigned int old = atomicAdd(&g_ticket, 1u);
        slast = (old == 511u) ? 1 : 0;
    }
    __syncthreads();
    if (slast) {
        __threadfence();
        float v = ldcg(&g_partial[tid]);               // L2-coherent read
        #pragma unroll
        for (int o = 16; o; o >>= 1) v += __shfl_xor_sync(0xFFFFFFFFu, v, o);
        if (lane == 0) s2[w] = v;
        __syncthreads();
        if (tid == 0) {
            float s = 0.f;
            #pragma unroll
            for (int i = 0; i < 16; i++) s += s2[i];
            float loss = -(s / (float)N_ITEMS);
            for (int i = BATCHSZ; i < out_size; i++) out[i] = loss;
            g_ticket = 0;                              // deterministic replay
        }
    }
}

// ---------------- launch ----------------------------------------------------
extern "C" void kernel_launch(void* const* d_in, const int* in_sizes, int n_in,
                              void* d_out, int out_size) {
    const int*   idx    = (const int*)d_in[0];
    const int*   labels = (const int*)d_in[1];
    const float* emb    = (const float*)d_in[2];
    const float* w      = (const float*)d_in[3];
    const float* b      = (const float*)d_in[4];
    float* out = (float*)d_out;

    const int SMEM = 65536 + 16 * 64 * 4 + 2 * 128 * 4;   // 70656 B
    cudaFuncSetAttribute(supcon_kernel, cudaFuncAttributeMaxDynamicSharedMemorySize, SMEM);

    prep_kernel<<<780, 256>>>(emb, idx, w, b, out);
    classsum_kernel<<<128, 512>>>(labels);
    supcon_kernel<<<GRID_SY, 512, SMEM>>>();
    lossrow_kernel<<<512, 512>>>(labels, out, out_size);
}

// round 16
// speedup vs baseline: 1.3200x; 1.1030x over previous
#include <cuda_runtime.h>
#include <cuda_fp16.h>
#include <cstdint>
#include <math.h>

#define N_ITEMS 8192
#define DIM     64
#define BATCHSZ 4096
#define LN2F    0.69314718055994531f
#define INV_T   14.285714285714286f
#define ITLG2E  20.609947181438156f   /* (1/0.07) * log2(e) */
#define NTILES  2080                  /* 64*65/2 upper-triangle 128x128 tiles */
#define GRID_SY 304                   /* 2 CTAs/SM x 152 SMs */
#define NCLS    128                   /* classsum tail CTAs (64 rows each) */

// ---------------- device scratch (no allocations allowed) ----------------
__device__ uint32_t g_fh[N_ITEMS * 32];   // normalized rows, half2-packed [row][32]
__device__ float    g_Z[N_ITEMS];         // exp-sums (atomic accumulated)
__device__ float    g_S[56 * 64];         // per-class feature sums
__device__ int      g_N[56];              // per-class counts
__device__ float    g_partial[256];       // per-CTA loss partials
__device__ unsigned int g_ticket = 0;     // last-CTA ticket (reset each run)

// ---------------- helpers --------------------------------------------------
static __device__ __forceinline__ uint32_t smem_u32(const void* p) {
    uint32_t a;
    asm("{ .reg .u64 t; cvta.to.shared.u64 t, %1; cvt.u32.u64 %0, t; }" : "=r"(a) : "l"(p));
    return a;
}
static __device__ __forceinline__ float ex2f(float x) {
    float y; asm("ex2.approx.ftz.f32 %0, %1;" : "=f"(y) : "f"(x)); return y;
}
static __device__ __forceinline__ float lg2f(float x) {
    float y; asm("lg2.approx.ftz.f32 %0, %1;" : "=f"(y) : "f"(x)); return y;
}
static __device__ __forceinline__ float ldcg(const float* p) {
    float v; asm volatile("ld.global.cg.f32 %0, [%1];" : "=f"(v) : "l"(p)); return v;
}
static __device__ __forceinline__ void cp16(uint32_t dst, const void* src) {
    asm volatile("cp.async.cg.shared.global [%0], [%1], 16;" :: "r"(dst), "l"(src));
}
#define CP_COMMIT() asm volatile("cp.async.commit_group;" ::: "memory")
static __device__ __forceinline__ void ldsm4(uint32_t* r, uint32_t addr) {
    asm volatile("ldmatrix.sync.aligned.m8n8.x4.shared.b16 {%0,%1,%2,%3}, [%4];"
                 : "=r"(r[0]), "=r"(r[1]), "=r"(r[2]), "=r"(r[3]) : "r"(addr));
}
static __device__ __forceinline__ void mma16816(float* d, const uint32_t* a,
                                                uint32_t b0, uint32_t b1) {
    asm volatile("mma.sync.aligned.m16n8k16.row.col.f32.f16.f16.f32 "
                 "{%0,%1,%2,%3}, {%4,%5,%6,%7}, {%8,%9}, {%0,%1,%2,%3};"
                 : "+f"(d[0]), "+f"(d[1]), "+f"(d[2]), "+f"(d[3])
                 : "r"(a[0]), "r"(a[1]), "r"(a[2]), "r"(a[3]), "r"(b0), "r"(b1));
}

// ---------------- kernel 1: normalize + rating + zero scratch --------------
__global__ __launch_bounds__(256) void prep_kernel(const float* __restrict__ emb,
                                                   const int* __restrict__ idx,
                                                   const float* __restrict__ w,
                                                   const float* __restrict__ bias,
                                                   float* __restrict__ out) {
    int bid = blockIdx.x;
    int hw  = threadIdx.x >> 4;      // half-warp in block (0..15)
    int hl  = threadIdx.x & 15;      // lane in half-warp
    if (bid < 512) {
        int row = bid * 16 + hw;
        float4 v = reinterpret_cast<const float4*>(emb + (size_t)row * DIM)[hl];
        float ss = v.x * v.x + v.y * v.y + v.z * v.z + v.w * v.w;
        #pragma unroll
        for (int o = 8; o; o >>= 1) ss += __shfl_xor_sync(0xFFFFFFFFu, ss, o);
        float inv = 1.0f / fmaxf(sqrtf(ss), 1e-12f);
        __half2 h0 = __floats2half2_rn(v.x * inv, v.y * inv);
        __half2 h1 = __floats2half2_rn(v.z * inv, v.w * inv);
        uint2 u;
        u.x = *reinterpret_cast<uint32_t*>(&h0);
        u.y = *reinterpret_cast<uint32_t*>(&h1);
        reinterpret_cast<uint2*>(g_fh + (size_t)row * 32)[hl] = u;
    } else if (bid < 768) {
        int r = (bid - 512) * 16 + hw;
        int it = idx[r];
        float4 v  = reinterpret_cast<const float4*>(emb + (size_t)it * DIM)[hl];
        float4 ww = reinterpret_cast<const float4*>(w)[hl];
        float s = v.x * ww.x + v.y * ww.y + v.z * ww.z + v.w * ww.w;
        #pragma unroll
        for (int o = 8; o; o >>= 1) s += __shfl_xor_sync(0xFFFFFFFFu, s, o);
        if (hl == 0) out[r] = 1.0f / (1.0f + __expf(-(s + bias[0])));
    } else {
        int flat = (bid - 768) * 1024 + threadIdx.x * 4;
        #pragma unroll
        for (int k = 0; k < 4; k++) {
            int f = flat + k;
            if (f < N_ITEMS) g_Z[f] = 0.f;
            else if (f < N_ITEMS + 3584) g_S[f - N_ITEMS] = 0.f;
            else if (f < N_ITEMS + 3584 + 56) g_N[f - N_ITEMS - 3584] = 0;
        }
    }
}

// ---------------- kernel 2: symmetric Z-only GEMM + classsum tail ----------
// Blocks [0,304): triangle tiles (chunked, A-band reuse).
// Blocks [304,432): per-class feature sums, 64 rows each (feeds lossrow only,
// so running them in the supcon tail is off the critical path).
static __device__ __forceinline__ void decode_tile(int w, int& ti, int& tj) {
    float disc = 16641.0f - 8.0f * (float)w;
    int t = (int)((129.0f - sqrtf(disc)) * 0.5f);
    if (t > 63) t = 63;
    if (t < 0) t = 0;
    while (t > 0 && (t * (129 - t)) / 2 > w) t--;
    while (t < 63 && ((t + 1) * (128 - t)) / 2 <= w) t++;
    ti = t;
    tj = t + (w - (t * (129 - t)) / 2);
}
static __device__ __forceinline__ void load_band(uint32_t sdst, int band, int tid) {
    const char* gsrc = (const char*)g_fh + (size_t)band * 16384;
    #pragma unroll
    for (int i = tid; i < 1024; i += 512) {
        uint32_t off = ((i >> 3) * 128) + ((i & 7) * 16);
        uint32_t sw  = off ^ ((off >> 3) & 0x70);
        cp16(sdst + sw, gsrc + off);
    }
}

__global__ __launch_bounds__(512, 2) void supcon_kernel(const int* __restrict__ labels) {
    extern __shared__ char dyn[];
    float* stage_col = reinterpret_cast<float*>(dyn + 65536);   // [16][64]
    float* stage_row = stage_col + 16 * 64;                     // [2][128]

    const int tid  = threadIdx.x;
    const int w    = tid >> 5;
    const int lane = tid & 31;

    // ---- classsum tail CTAs ----
    if (blockIdx.x >= GRID_SY) {
        int* sl = reinterpret_cast<int*>(dyn);
        int b = blockIdx.x - GRID_SY;
        int d = tid & 63, g = tid >> 6, c0 = g * 7;
        if (tid < 64) sl[tid] = labels[b * 64 + tid];
        __syncthreads();
        float a[7] = {0, 0, 0, 0, 0, 0, 0};
        int   n[7] = {0, 0, 0, 0, 0, 0, 0};
        for (int r = 0; r < 64; r++) {
            int rel = sl[r] - c0;
            if ((unsigned)rel < 7u) {
                uint32_t p = g_fh[(size_t)(b * 64 + r) * 32 + (d >> 1)];
                __half2 h = *reinterpret_cast<__half2*>(&p);
                float v = (d & 1) ? __high2float(h) : __low2float(h);
                #pragma unroll
                for (int q = 0; q < 7; q++) if (rel == q) { a[q] += v; n[q]++; }
            }
        }
        #pragma unroll
        for (int q = 0; q < 7; q++) {
            atomicAdd(&g_S[(c0 + q) * 64 + d], a[q]);
            if (d == 0) atomicAdd(&g_N[c0 + q], n[q]);
        }
        return;
    }

    const int wr   = w & 7;
    const int wc   = w >> 3;
    const uint32_t sbase = smem_u32(dyn);
    const int bnoff = (((lane >> 4) & 1) << 3) + (lane & 7);
    const uint32_t bksel = (uint32_t)((lane >> 3) & 1);
    const float negM = -ITLG2E;

    const int start = (int)(((long long)blockIdx.x * NTILES) / GRID_SY);
    const int end   = (int)(((long long)(blockIdx.x + 1) * NTILES) / GRID_SY);

    int ti, tj;
    decode_tile(start, ti, tj);
    int aslot = 0, bslot = 0;
    bool bIsA = (ti == tj);
    load_band(sbase, ti, tid);
    if (!bIsA) load_band(sbase + 32768, tj, tid);
    CP_COMMIT();

    bool aNew = true;
    uint32_t ah[4][4];

    for (int job = start; job < end; job++) {
        bool loadA = false, loadB = false, nbIsA = bIsA;
        int tin = ti, tjn = tj;
        if (job + 1 < end) {
            decode_tile(job + 1, tin, tjn);
            nbIsA = (tin == tjn);
            loadA = (tin != ti);
            loadB = !nbIsA;
            if (loadA) load_band(sbase + (uint32_t)(aslot ^ 1) * 16384, tin, tid);
            if (loadB) load_band(sbase + 32768 + (uint32_t)(bslot ^ 1) * 16384, tjn, tid);
        }
        CP_COMMIT();
        asm volatile("cp.async.wait_group 1;" ::: "memory");
        __syncthreads();                      // current tile resident

        const uint32_t Ab = sbase + (uint32_t)aslot * 16384;
        const uint32_t Bb = bIsA ? Ab : (sbase + 32768 + (uint32_t)bslot * 16384);

        if (aNew) {
            int arow = wr * 16 + (lane & 15);
            uint32_t rbase = Ab + (uint32_t)arow * 128;
            #pragma unroll
            for (int ks = 0; ks < 4; ks++) {
                uint32_t c = (uint32_t)(ks * 2 + (lane >> 4));
                ldsm4(ah[ks], rbase + ((c ^ (arow & 7)) << 4));
            }
        }

        float rowZ0 = 0.f, rowZ1 = 0.f;
        #pragma unroll
        for (int ntp = 0; ntp < 4; ntp++) {
            float a0[4] = {0.f, 0.f, 0.f, 0.f};
            float a1[4] = {0.f, 0.f, 0.f, 0.f};
            int n = wc * 64 + ntp * 16 + bnoff;
            uint32_t nb = Bb + (uint32_t)n * 128;
            #pragma unroll
            for (int ks = 0; ks < 4; ks++) {
                uint32_t c = (uint32_t)(ks * 2) + bksel;
                uint32_t bb[4];
                ldsm4(bb, nb + ((c ^ (n & 7)) << 4));
                mma16816(a0, ah[ks], bb[0], bb[1]);
                mma16816(a1, ah[ks], bb[2], bb[3]);
            }
            float e00 = ex2f(fmaf(a0[0], ITLG2E, negM));
            float e01 = ex2f(fmaf(a0[1], ITLG2E, negM));
            float e10 = ex2f(fmaf(a0[2], ITLG2E, negM));
            float e11 = ex2f(fmaf(a0[3], ITLG2E, negM));
            float f00 = ex2f(fmaf(a1[0], ITLG2E, negM));
            float f01 = ex2f(fmaf(a1[1], ITLG2E, negM));
            float f10 = ex2f(fmaf(a1[2], ITLG2E, negM));
            float f11 = ex2f(fmaf(a1[3], ITLG2E, negM));
            rowZ0 += (e00 + e01) + (f00 + f01);
            rowZ1 += (e10 + e11) + (f10 + f11);
            float cz0 = e00 + e10, cz1 = e01 + e11;
            float cz2 = f00 + f10, cz3 = f01 + f11;
            #pragma unroll
            for (int off = 4; off <= 16; off <<= 1) {
                cz0 += __shfl_xor_sync(0xFFFFFFFFu, cz0, off);
                cz1 += __shfl_xor_sync(0xFFFFFFFFu, cz1, off);
                cz2 += __shfl_xor_sync(0xFFFFFFFFu, cz2, off);
                cz3 += __shfl_xor_sync(0xFFFFFFFFu, cz3, off);
            }
            if (lane < 4) {
                int cl = ntp * 16 + 2 * lane;
                stage_col[w * 64 + cl]     = cz0;
                stage_col[w * 64 + cl + 1] = cz1;
                stage_col[w * 64 + cl + 8] = cz2;
                stage_col[w * 64 + cl + 9] = cz3;
            }
        }
        #pragma unroll
        for (int off = 1; off <= 2; off <<= 1) {
            rowZ0 += __shfl_xor_sync(0xFFFFFFFFu, rowZ0, off);
            rowZ1 += __shfl_xor_sync(0xFFFFFFFFu, rowZ1, off);
        }
        if ((lane & 3) == 0) {
            int r0 = wr * 16 + (lane >> 2);
            stage_row[wc * 128 + r0]     = rowZ0;
            stage_row[wc * 128 + r0 + 8] = rowZ1;
        }
        __syncthreads();                      // stages complete
        if (tid < 128) {
            if (ti != tj) {
                int whalf = (tid >> 6) * 8;
                int cl = tid & 63;
                float v = 0.f;
                #pragma unroll
                for (int k = 0; k < 8; k++) v += stage_col[(whalf + k) * 64 + cl];
                atomicAdd(&g_Z[tj * 128 + tid], v);
            }
        } else if (tid < 256) {
            int r = tid - 128;
            atomicAdd(&g_Z[ti * 128 + r], stage_row[r] + stage_row[128 + r]);
        }
        if (loadA) aslot ^= 1;
        if (loadB) bslot ^= 1;
        aNew = loadA;
        ti = tin; tj = tjn; bIsA = nbIsA;
    }
}

// ---------------- kernel 3: per-row loss (2 rows/warp) + fused finalize -----
// 256 CTAs x 512 thr (16 warps); warp handles rows 2w, 2w+1 of its block.
__global__ __launch_bounds__(512) void lossrow_kernel(const int* __restrict__ labels,
                                                      float* __restrict__ out,
                                                      int out_size) {
    __shared__ float red[16];
    __shared__ int   slast;
    __shared__ float s2[16];
    int tid  = threadIdx.x;
    int w    = tid >> 5;
    int lane = tid & 31;
    int r0   = blockIdx.x * 32 + w * 2;
    int r1   = r0 + 1;

    int lab0 = labels[r0], lab1 = labels[r1];
    uint32_t p0 = g_fh[(size_t)r0 * 32 + lane];
    uint32_t p1 = g_fh[(size_t)r1 * 32 + lane];
    __half2 h0 = *reinterpret_cast<__half2*>(&p0);
    __half2 h1 = *reinterpret_cast<__half2*>(&p1);
    float a0 = __low2float(h0), a1 = __high2float(h0);
    float b0 = __low2float(h1), b1 = __high2float(h1);
    float sA = a0 * a0 + a1 * a1;
    float sB = b0 * b0 + b1 * b1;
    float dA = a0 * g_S[lab0 * 64 + 2 * lane] + a1 * g_S[lab0 * 64 + 2 * lane + 1];
    float dB = b0 * g_S[lab1 * 64 + 2 * lane] + b1 * g_S[lab1 * 64 + 2 * lane + 1];
    #pragma unroll
    for (int o = 16; o; o >>= 1) {
        sA += __shfl_xor_sync(0xFFFFFFFFu, sA, o);
        dA += __shfl_xor_sync(0xFFFFFFFFu, dA, o);
        sB += __shfl_xor_sync(0xFFFFFFFFu, sB, o);
        dB += __shfl_xor_sync(0xFFFFFFFFu, dB, o);
    }
    if (lane == 0) {
        float CcA = (float)g_N[lab0] - 1.0f;
        float CcB = (float)g_N[lab1] - 1.0f;
        float ZA  = g_Z[r0] - ex2f((sA - 1.0f) * ITLG2E);
        float ZB  = g_Z[r1] - ex2f((sB - 1.0f) * ITLG2E);
        float PA  = (dA - sA - CcA) * INV_T;
        float PB  = (dB - sB - CcB) * INV_T;
        float lA  = lg2f(ZA + 1e-6f) * LN2F;
        float lB  = lg2f(ZB + 1e-6f) * LN2F;
        red[w] = (PA - CcA * lA) / (CcA + 1e-6f) + (PB - CcB * lB) / (CcB + 1e-6f);
    }
    __syncthreads();
    if (tid == 0) {
        float s = 0.f;
        #pragma unroll
        for (int i = 0; i < 16; i++) s += red[i];
        g_partial[blockIdx.x] = s;
        __threadfence();
        unsigned int old = atomicAdd(&g_ticket, 1u);
        slast = (old == 255u) ? 1 : 0;
    }
    __syncthreads();
    if (slast) {
        __threadfence();
        float v = (tid < 256) ? ldcg(&g_partial[tid]) : 0.f;
        #pragma unroll
        for (int o = 16; o; o >>= 1) v += __shfl_xor_sync(0xFFFFFFFFu, v, o);
        if (lane == 0) s2[w] = v;
        __syncthreads();
        if (tid == 0) {
            float s = 0.f;
            #pragma unroll
            for (int i = 0; i < 16; i++) s += s2[i];
            float loss = -(s / (float)N_ITEMS);
            for (int i = BATCHSZ; i < out_size; i++) out[i] = loss;
            g_ticket = 0;                              // deterministic replay
        }
    }
}

// ---------------- launch ----------------------------------------------------
extern "C" void kernel_launch(void* const* d_in, const int* in_sizes, int n_in,
                              void* d_out, int out_size) {
    const int*   idx    = (const int*)d_in[0];
    const int*   labels = (const int*)d_in[1];
    const float* emb    = (const float*)d_in[2];
    const float* w      = (const float*)d_in[3];
    const float* b      = (const float*)d_in[4];
    float* out = (float*)d_out;

    const int SMEM = 65536 + 16 * 64 * 4 + 2 * 128 * 4;   // 70656 B
    cudaFuncSetAttribute(supcon_kernel, cudaFuncAttributeMaxDynamicSharedMemorySize, SMEM);

    prep_kernel<<<780, 256>>>(emb, idx, w, b, out);
    supcon_kernel<<<GRID_SY + NCLS, 512, SMEM>>>(labels);
    lossrow_kernel<<<256, 512>>>(labels, out, out_size);
}

// round 17
// speedup vs baseline: 1.3429x; 1.0173x over previous
#include <cuda_runtime.h>
#include <cuda_fp16.h>
#include <cstdint>
#include <math.h>

#define N_ITEMS 8192
#define DIM     64
#define BATCHSZ 4096
#define LN2F    0.69314718055994531f
#define INV_T   14.285714285714286f
#define ITLG2E  20.609947181438156f   /* (1/0.07) * log2(e) */
#define NTILES  2080                  /* 64*65/2 upper-triangle 128x128 tiles */
#define GRID_SY 304                   /* 2 CTAs/SM x 152 SMs */
#define NCLS    128                   /* classsum tail CTAs (64 rows each) */

// ---------------- device scratch (no allocations allowed) ----------------
__device__ uint32_t g_fh[N_ITEMS * 32];   // normalized rows, half2-packed [row][32]
__device__ float    g_Z[N_ITEMS];         // exp-sums (atomic accumulated)
__device__ float    g_S[56 * 64];         // per-class feature sums
__device__ int      g_N[56];              // per-class counts
__device__ float    g_partial[256];       // per-CTA loss partials
__device__ unsigned int g_ticket = 0;     // last-CTA ticket (reset each run)

// ---------------- helpers --------------------------------------------------
static __device__ __forceinline__ uint32_t smem_u32(const void* p) {
    uint32_t a;
    asm("{ .reg .u64 t; cvta.to.shared.u64 t, %1; cvt.u32.u64 %0, t; }" : "=r"(a) : "l"(p));
    return a;
}
static __device__ __forceinline__ float ex2f(float x) {
    float y; asm("ex2.approx.ftz.f32 %0, %1;" : "=f"(y) : "f"(x)); return y;
}
static __device__ __forceinline__ float lg2f(float x) {
    float y; asm("lg2.approx.ftz.f32 %0, %1;" : "=f"(y) : "f"(x)); return y;
}
static __device__ __forceinline__ float ldcg(const float* p) {
    float v; asm volatile("ld.global.cg.f32 %0, [%1];" : "=f"(v) : "l"(p)); return v;
}
static __device__ __forceinline__ void cp16(uint32_t dst, const void* src) {
    asm volatile("cp.async.cg.shared.global [%0], [%1], 16;" :: "r"(dst), "l"(src));
}
#define CP_COMMIT() asm volatile("cp.async.commit_group;" ::: "memory")
static __device__ __forceinline__ void ldsm4(uint32_t* r, uint32_t addr) {
    asm volatile("ldmatrix.sync.aligned.m8n8.x4.shared.b16 {%0,%1,%2,%3}, [%4];"
                 : "=r"(r[0]), "=r"(r[1]), "=r"(r[2]), "=r"(r[3]) : "r"(addr));
}
static __device__ __forceinline__ void mma16816(float* d, const uint32_t* a,
                                                uint32_t b0, uint32_t b1) {
    asm volatile("mma.sync.aligned.m16n8k16.row.col.f32.f16.f16.f32 "
                 "{%0,%1,%2,%3}, {%4,%5,%6,%7}, {%8,%9}, {%0,%1,%2,%3};"
                 : "+f"(d[0]), "+f"(d[1]), "+f"(d[2]), "+f"(d[3])
                 : "r"(a[0]), "r"(a[1]), "r"(a[2]), "r"(a[3]), "r"(b0), "r"(b1));
}

// ---------------- kernel 1: normalize + rating + zero scratch --------------
// 2 rows per half-warp (doubled MLP/ILP): blocks [0,256) normalize 32 rows,
// [256,384) rating 32 each, [384,396) zero scratch. 396 CTAs.
__global__ __launch_bounds__(256) void prep_kernel(const float* __restrict__ emb,
                                                   const int* __restrict__ idx,
                                                   const float* __restrict__ w,
                                                   const float* __restrict__ bias,
                                                   float* __restrict__ out) {
    int bid = blockIdx.x;
    int hw  = threadIdx.x >> 4;      // half-warp in block (0..15)
    int hl  = threadIdx.x & 15;      // lane in half-warp
    if (bid < 256) {
        int row0 = bid * 32 + hw * 2;
        int row1 = row0 + 1;
        float4 v0 = reinterpret_cast<const float4*>(emb + (size_t)row0 * DIM)[hl];
        float4 v1 = reinterpret_cast<const float4*>(emb + (size_t)row1 * DIM)[hl];
        float s0 = v0.x * v0.x + v0.y * v0.y + v0.z * v0.z + v0.w * v0.w;
        float s1 = v1.x * v1.x + v1.y * v1.y + v1.z * v1.z + v1.w * v1.w;
        #pragma unroll
        for (int o = 8; o; o >>= 1) {
            s0 += __shfl_xor_sync(0xFFFFFFFFu, s0, o);
            s1 += __shfl_xor_sync(0xFFFFFFFFu, s1, o);
        }
        float i0 = 1.0f / fmaxf(sqrtf(s0), 1e-12f);
        float i1 = 1.0f / fmaxf(sqrtf(s1), 1e-12f);
        __half2 a0 = __floats2half2_rn(v0.x * i0, v0.y * i0);
        __half2 a1 = __floats2half2_rn(v0.z * i0, v0.w * i0);
        __half2 b0 = __floats2half2_rn(v1.x * i1, v1.y * i1);
        __half2 b1 = __floats2half2_rn(v1.z * i1, v1.w * i1);
        uint2 u0, u1;
        u0.x = *reinterpret_cast<uint32_t*>(&a0);
        u0.y = *reinterpret_cast<uint32_t*>(&a1);
        u1.x = *reinterpret_cast<uint32_t*>(&b0);
        u1.y = *reinterpret_cast<uint32_t*>(&b1);
        reinterpret_cast<uint2*>(g_fh + (size_t)row0 * 32)[hl] = u0;
        reinterpret_cast<uint2*>(g_fh + (size_t)row1 * 32)[hl] = u1;
    } else if (bid < 384) {
        int r0 = (bid - 256) * 32 + hw * 2;
        int r1 = r0 + 1;
        int it0 = idx[r0], it1 = idx[r1];
        float4 v0 = reinterpret_cast<const float4*>(emb + (size_t)it0 * DIM)[hl];
        float4 v1 = reinterpret_cast<const float4*>(emb + (size_t)it1 * DIM)[hl];
        float4 ww = reinterpret_cast<const float4*>(w)[hl];
        float s0 = v0.x * ww.x + v0.y * ww.y + v0.z * ww.z + v0.w * ww.w;
        float s1 = v1.x * ww.x + v1.y * ww.y + v1.z * ww.z + v1.w * ww.w;
        #pragma unroll
        for (int o = 8; o; o >>= 1) {
            s0 += __shfl_xor_sync(0xFFFFFFFFu, s0, o);
            s1 += __shfl_xor_sync(0xFFFFFFFFu, s1, o);
        }
        if (hl == 0) {
            float bb = bias[0];
            out[r0] = 1.0f / (1.0f + __expf(-(s0 + bb)));
            out[r1] = 1.0f / (1.0f + __expf(-(s1 + bb)));
        }
    } else {
        int flat = (bid - 384) * 1024 + threadIdx.x * 4;
        #pragma unroll
        for (int k = 0; k < 4; k++) {
            int f = flat + k;
            if (f < N_ITEMS) g_Z[f] = 0.f;
            else if (f < N_ITEMS + 3584) g_S[f - N_ITEMS] = 0.f;
            else if (f < N_ITEMS + 3584 + 56) g_N[f - N_ITEMS - 3584] = 0;
        }
    }
}

// ---------------- kernel 2: symmetric Z-only GEMM + classsum tail ----------
static __device__ __forceinline__ void decode_tile(int w, int& ti, int& tj) {
    float disc = 16641.0f - 8.0f * (float)w;
    int t = (int)((129.0f - sqrtf(disc)) * 0.5f);
    if (t > 63) t = 63;
    if (t < 0) t = 0;
    while (t > 0 && (t * (129 - t)) / 2 > w) t--;
    while (t < 63 && ((t + 1) * (128 - t)) / 2 <= w) t++;
    ti = t;
    tj = t + (w - (t * (129 - t)) / 2);
}
static __device__ __forceinline__ void load_band(uint32_t sdst, int band, int tid) {
    const char* gsrc = (const char*)g_fh + (size_t)band * 16384;
    #pragma unroll
    for (int i = tid; i < 1024; i += 512) {
        uint32_t off = ((i >> 3) * 128) + ((i & 7) * 16);
        uint32_t sw  = off ^ ((off >> 3) & 0x70);
        cp16(sdst + sw, gsrc + off);
    }
}

__global__ __launch_bounds__(512, 2) void supcon_kernel(const int* __restrict__ labels) {
    extern __shared__ char dyn[];
    float* stage_col = reinterpret_cast<float*>(dyn + 65536);   // [16][64]
    float* stage_row = stage_col + 16 * 64;                     // [2][128]

    const int tid  = threadIdx.x;
    const int w    = tid >> 5;
    const int lane = tid & 31;

    // ---- classsum tail CTAs ----
    if (blockIdx.x >= GRID_SY) {
        int* sl = reinterpret_cast<int*>(dyn);
        int b = blockIdx.x - GRID_SY;
        int d = tid & 63, g = tid >> 6, c0 = g * 7;
        if (tid < 64) sl[tid] = labels[b * 64 + tid];
        __syncthreads();
        float a[7] = {0, 0, 0, 0, 0, 0, 0};
        int   n[7] = {0, 0, 0, 0, 0, 0, 0};
        for (int r = 0; r < 64; r++) {
            int rel = sl[r] - c0;
            if ((unsigned)rel < 7u) {
                uint32_t p = g_fh[(size_t)(b * 64 + r) * 32 + (d >> 1)];
                __half2 h = *reinterpret_cast<__half2*>(&p);
                float v = (d & 1) ? __high2float(h) : __low2float(h);
                #pragma unroll
                for (int q = 0; q < 7; q++) if (rel == q) { a[q] += v; n[q]++; }
            }
        }
        #pragma unroll
        for (int q = 0; q < 7; q++) {
            atomicAdd(&g_S[(c0 + q) * 64 + d], a[q]);
            if (d == 0) atomicAdd(&g_N[c0 + q], n[q]);
        }
        return;
    }

    const int wr   = w & 7;
    const int wc   = w >> 3;
    const uint32_t sbase = smem_u32(dyn);
    const int bnoff = (((lane >> 4) & 1) << 3) + (lane & 7);
    const uint32_t bksel = (uint32_t)((lane >> 3) & 1);
    const float negM = -ITLG2E;

    const int start = (int)(((long long)blockIdx.x * NTILES) / GRID_SY);
    const int end   = (int)(((long long)(blockIdx.x + 1) * NTILES) / GRID_SY);

    int ti, tj;
    decode_tile(start, ti, tj);
    int aslot = 0, bslot = 0;
    bool bIsA = (ti == tj);
    load_band(sbase, ti, tid);
    if (!bIsA) load_band(sbase + 32768, tj, tid);
    CP_COMMIT();

    bool aNew = true;
    uint32_t ah[4][4];

    for (int job = start; job < end; job++) {
        bool loadA = false, loadB = false, nbIsA = bIsA;
        int tin = ti, tjn = tj;
        if (job + 1 < end) {
            decode_tile(job + 1, tin, tjn);
            nbIsA = (tin == tjn);
            loadA = (tin != ti);
            loadB = !nbIsA;
            if (loadA) load_band(sbase + (uint32_t)(aslot ^ 1) * 16384, tin, tid);
            if (loadB) load_band(sbase + 32768 + (uint32_t)(bslot ^ 1) * 16384, tjn, tid);
        }
        CP_COMMIT();
        asm volatile("cp.async.wait_group 1;" ::: "memory");
        __syncthreads();                      // current tile resident

        const uint32_t Ab = sbase + (uint32_t)aslot * 16384;
        const uint32_t Bb = bIsA ? Ab : (sbase + 32768 + (uint32_t)bslot * 16384);

        if (aNew) {
            int arow = wr * 16 + (lane & 15);
            uint32_t rbase = Ab + (uint32_t)arow * 128;
            #pragma unroll
            for (int ks = 0; ks < 4; ks++) {
                uint32_t c = (uint32_t)(ks * 2 + (lane >> 4));
                ldsm4(ah[ks], rbase + ((c ^ (arow & 7)) << 4));
            }
        }

        float rowZ0 = 0.f, rowZ1 = 0.f;
        #pragma unroll
        for (int ntp = 0; ntp < 4; ntp++) {
            float a0[4] = {0.f, 0.f, 0.f, 0.f};
            float a1[4] = {0.f, 0.f, 0.f, 0.f};
            int n = wc * 64 + ntp * 16 + bnoff;
            uint32_t nb = Bb + (uint32_t)n * 128;
            #pragma unroll
            for (int ks = 0; ks < 4; ks++) {
                uint32_t c = (uint32_t)(ks * 2) + bksel;
                uint32_t bb[4];
                ldsm4(bb, nb + ((c ^ (n & 7)) << 4));
                mma16816(a0, ah[ks], bb[0], bb[1]);
                mma16816(a1, ah[ks], bb[2], bb[3]);
            }
            float e00 = ex2f(fmaf(a0[0], ITLG2E, negM));
            float e01 = ex2f(fmaf(a0[1], ITLG2E, negM));
            float e10 = ex2f(fmaf(a0[2], ITLG2E, negM));
            float e11 = ex2f(fmaf(a0[3], ITLG2E, negM));
            float f00 = ex2f(fmaf(a1[0], ITLG2E, negM));
            float f01 = ex2f(fmaf(a1[1], ITLG2E, negM));
            float f10 = ex2f(fmaf(a1[2], ITLG2E, negM));
            float f11 = ex2f(fmaf(a1[3], ITLG2E, negM));
            rowZ0 += (e00 + e01) + (f00 + f01);
            rowZ1 += (e10 + e11) + (f10 + f11);
            float cz0 = e00 + e10, cz1 = e01 + e11;
            float cz2 = f00 + f10, cz3 = f01 + f11;
            #pragma unroll
            for (int off = 4; off <= 16; off <<= 1) {
                cz0 += __shfl_xor_sync(0xFFFFFFFFu, cz0, off);
                cz1 += __shfl_xor_sync(0xFFFFFFFFu, cz1, off);
                cz2 += __shfl_xor_sync(0xFFFFFFFFu, cz2, off);
                cz3 += __shfl_xor_sync(0xFFFFFFFFu, cz3, off);
            }
            if (lane < 4) {
                int cl = ntp * 16 + 2 * lane;
                stage_col[w * 64 + cl]     = cz0;
                stage_col[w * 64 + cl + 1] = cz1;
                stage_col[w * 64 + cl + 8] = cz2;
                stage_col[w * 64 + cl + 9] = cz3;
            }
        }
        #pragma unroll
        for (int off = 1; off <= 2; off <<= 1) {
            rowZ0 += __shfl_xor_sync(0xFFFFFFFFu, rowZ0, off);
            rowZ1 += __shfl_xor_sync(0xFFFFFFFFu, rowZ1, off);
        }
        if ((lane & 3) == 0) {
            int r0 = wr * 16 + (lane >> 2);
            stage_row[wc * 128 + r0]     = rowZ0;
            stage_row[wc * 128 + r0 + 8] = rowZ1;
        }
        __syncthreads();                      // stages complete
        if (tid < 128) {
            if (ti != tj) {
                int whalf = (tid >> 6) * 8;
                int cl = tid & 63;
                float v = 0.f;
                #pragma unroll
                for (int k = 0; k < 8; k++) v += stage_col[(whalf + k) * 64 + cl];
                atomicAdd(&g_Z[tj * 128 + tid], v);
            }
        } else if (tid < 256) {
            int r = tid - 128;
            atomicAdd(&g_Z[ti * 128 + r], stage_row[r] + stage_row[128 + r]);
        }
        if (loadA) aslot ^= 1;
        if (loadB) bslot ^= 1;
        aNew = loadA;
        ti = tin; tj = tjn; bIsA = nbIsA;
    }
}

// ---------------- kernel 3: per-row loss (2 rows/warp) + fused finalize -----
__global__ __launch_bounds__(512) void lossrow_kernel(const int* __restrict__ labels,
                                                      float* __restrict__ out,
                                                      int out_size) {
    __shared__ float red[16];
    __shared__ int   slast;
    __shared__ float s2[16];
    int tid  = threadIdx.x;
    int w    = tid >> 5;
    int lane = tid & 31;
    int r0   = blockIdx.x * 32 + w * 2;
    int r1   = r0 + 1;

    int lab0 = labels[r0], lab1 = labels[r1];
    uint32_t p0 = g_fh[(size_t)r0 * 32 + lane];
    uint32_t p1 = g_fh[(size_t)r1 * 32 + lane];
    __half2 h0 = *reinterpret_cast<__half2*>(&p0);
    __half2 h1 = *reinterpret_cast<__half2*>(&p1);
    float a0 = __low2float(h0), a1 = __high2float(h0);
    float b0 = __low2float(h1), b1 = __high2float(h1);
    float sA = a0 * a0 + a1 * a1;
    float sB = b0 * b0 + b1 * b1;
    float dA = a0 * g_S[lab0 * 64 + 2 * lane] + a1 * g_S[lab0 * 64 + 2 * lane + 1];
    float dB = b0 * g_S[lab1 * 64 + 2 * lane] + b1 * g_S[lab1 * 64 + 2 * lane + 1];
    #pragma unroll
    for (int o = 16; o; o >>= 1) {
        sA += __shfl_xor_sync(0xFFFFFFFFu, sA, o);
        dA += __shfl_xor_sync(0xFFFFFFFFu, dA, o);
        sB += __shfl_xor_sync(0xFFFFFFFFu, sB, o);
        dB += __shfl_xor_sync(0xFFFFFFFFu, dB, o);
    }
    if (lane == 0) {
        float CcA = (float)g_N[lab0] - 1.0f;
        float CcB = (float)g_N[lab1] - 1.0f;
        float ZA  = g_Z[r0] - ex2f((sA - 1.0f) * ITLG2E);
        float ZB  = g_Z[r1] - ex2f((sB - 1.0f) * ITLG2E);
        float PA  = (dA - sA - CcA) * INV_T;
        float PB  = (dB - sB - CcB) * INV_T;
        float lA  = lg2f(ZA + 1e-6f) * LN2F;
        float lB  = lg2f(ZB + 1e-6f) * LN2F;
        red[w] = (PA - CcA * lA) / (CcA + 1e-6f) + (PB - CcB * lB) / (CcB + 1e-6f);
    }
    __syncthreads();
    if (tid == 0) {
        float s = 0.f;
        #pragma unroll
        for (int i = 0; i < 16; i++) s += red[i];
        g_partial[blockIdx.x] = s;
        __threadfence();
        unsigned int old = atomicAdd(&g_ticket, 1u);
        slast = (old == 255u) ? 1 : 0;
    }
    __syncthreads();
    if (slast) {
        __threadfence();
        float v = (tid < 256) ? ldcg(&g_partial[tid]) : 0.f;
        #pragma unroll
        for (int o = 16; o; o >>= 1) v += __shfl_xor_sync(0xFFFFFFFFu, v, o);
        if (lane == 0) s2[w] = v;
        __syncthreads();
        if (tid == 0) {
            float s = 0.f;
            #pragma unroll
            for (int i = 0; i < 16; i++) s += s2[i];
            float loss = -(s / (float)N_ITEMS);
            for (int i = BATCHSZ; i < out_size; i++) out[i] = loss;
            g_ticket = 0;                              // deterministic replay
        }
    }
}

// ---------------- launch ----------------------------------------------------
extern "C" void kernel_launch(void* const* d_in, const int* in_sizes, int n_in,
                              void* d_out, int out_size) {
    const int*   idx    = (const int*)d_in[0];
    const int*   labels = (const int*)d_in[1];
    const float* emb    = (const float*)d_in[2];
    const float* w      = (const float*)d_in[3];
    const float* b      = (const float*)d_in[4];
    float* out = (float*)d_out;

    const int SMEM = 65536 + 16 * 64 * 4 + 2 * 128 * 4;   // 70656 B
    cudaFuncSetAttribute(supcon_kernel, cudaFuncAttributeMaxDynamicSharedMemorySize, SMEM);

    prep_kernel<<<396, 256>>>(emb, idx, w, b, out);
    supcon_kernel<<<GRID_SY + NCLS, 512, SMEM>>>(labels);
    lossrow_kernel<<<256, 512>>>(labels, out, out_size);
}